// round 11
// baseline (speedup 1.0000x reference)
#include <cuda_runtime.h>
#include <cstdint>

// field[i,j] = sum_n w_n * ox_n[i] * oy_n[j] / (lx*ly)
// dims < 3/G per axis -> footprint <= 4x4 cells.
// 1 thread per rect; cell-unit coords; aligned-quad red.global.add.v4.f32.
// R9: 128-thread blocks (wave-tail quantization 5.28 -> 10.56 waves),
//     cudaMemsetAsync zero-fill, quad-0-always-live simplification.

#define G 256

__device__ __forceinline__ void red_v4(float* addr, float v0, float v1, float v2, float v3) {
    asm volatile("red.global.add.v4.f32 [%0], {%1, %2, %3, %4};"
                 :: "l"(addr), "f"(v0), "f"(v1), "f"(v2), "f"(v3) : "memory");
}

__global__ void __launch_bounds__(128) charge_scatter_kernel(
    const float4* __restrict__ boundary,  // [xmin, ymin, xmax, ymax]
    const float2* __restrict__ xy,        // [N]
    const float2* __restrict__ dims,      // [N]
    const float* __restrict__ cw,         // [N]
    float* __restrict__ field,            // [G*G]
    int n)
{
    int r = blockIdx.x * blockDim.x + threadIdx.x;
    if (r >= n) return;

    const float2 p = xy[r];
    const float2 d = dims[r];
    const float w = cw[r];

    const float4 b = *boundary;
    const float inv_lx = __frcp_rn((b.z - b.x) * (1.0f / G));  // exact: lx = 2^-8
    const float inv_ly = __frcp_rn((b.w - b.y) * (1.0f / G));

    // Cell-unit coordinates (x0u,y0u in [0,G); x1u,y1u < G+3)
    const float x0u = (p.x - b.x) * inv_lx;
    const float x1u = (p.x + d.x - b.x) * inv_lx;
    const float y0u = (p.y - b.y) * inv_ly;
    const float y1u = (p.y + d.y - b.y) * inv_ly;

    const int i0 = max((int)floorf(x0u), 0);
    const int j0 = max((int)floorf(y0u), 0);
    const int jq0 = j0 & ~3;              // aligned quad base, <= 252: always in grid
    const int jq1 = jq0 + 4;

    // Quad 0 y-overlaps: always contains the footprint start.
    float q0[4];
    #pragma unroll
    for (int k = 0; k < 4; k++) {
        float c = (float)(jq0 + k);
        q0[k] = fmaxf(fminf(y1u, c + 1.0f) - fmaxf(y0u, c), 0.0f);
    }
    // Quad 1 needed iff footprint extends past jq1 and jq1 is in-grid.
    const bool use1 = (jq1 < G) && (y1u > (float)jq1);
    float q1[4];
    #pragma unroll
    for (int k = 0; k < 4; k++) {
        float c = (float)(jq1 + k);
        q1[k] = fmaxf(fminf(y1u, c + 1.0f) - fmaxf(y0u, c), 0.0f);
    }

    #pragma unroll
    for (int s = 0; s < 4; s++) {
        int i = i0 + s;
        float fi = (float)i;
        float oxu = fmaxf(fminf(x1u, fi + 1.0f) - fmaxf(x0u, fi), 0.0f);
        float sx = w * oxu;
        if (i < G && sx != 0.0f) {
            float* rowbase = field + i * G;
            red_v4(rowbase + jq0, sx * q0[0], sx * q0[1], sx * q0[2], sx * q0[3]);
            if (use1) red_v4(rowbase + jq1, sx * q1[0], sx * q1[1], sx * q1[2], sx * q1[3]);
        }
    }
}

extern "C" void kernel_launch(void* const* d_in, const int* in_sizes, int n_in,
                              void* d_out, int out_size) {
    const float4* boundary = (const float4*)d_in[0];
    const float2* xy       = (const float2*)d_in[1];
    const float2* dims     = (const float2*)d_in[2];
    const float*  cw       = (const float*)d_in[3];
    float* field = (float*)d_out;

    const int n = in_sizes[3];          // N_RECTS

    // Zero d_out via memset node (graph-capturable, cheaper than a kernel).
    cudaMemsetAsync(field, 0, (size_t)out_size * sizeof(float), 0);

    charge_scatter_kernel<<<(n + 127) / 128, 128>>>(boundary, xy, dims, cw, field, n);
}

// round 13
// speedup vs baseline: 1.1881x; 1.1881x over previous
#include <cuda_runtime.h>
#include <cstdint>

// field[i,j] = sum_n w_n * ox_n[i] * oy_n[j] / (lx*ly)
// dims < 3/G per axis -> footprint <= 4x4 cells.
// R11: 2 rects per thread, float4-vectorized input loads (xy/dims pair-packed),
//      cell-unit coords, aligned-quad red.global.add.v4.f32 (fire-and-forget).
//      Zero-fill via tiny kernel (memset node measured slower in-graph).

#define G 256

__global__ void zero_field_kernel4(float4* __restrict__ out, int n4) {
    int i = blockIdx.x * blockDim.x + threadIdx.x;
    if (i < n4) out[i] = make_float4(0.f, 0.f, 0.f, 0.f);
}

__device__ __forceinline__ void red_v4(float* addr, float v0, float v1, float v2, float v3) {
    asm volatile("red.global.add.v4.f32 [%0], {%1, %2, %3, %4};"
                 :: "l"(addr), "f"(v0), "f"(v1), "f"(v2), "f"(v3) : "memory");
}

// Scatter one rect given cell-unit bounds.
__device__ __forceinline__ void scatter_rect(
    float x0u, float x1u, float y0u, float y1u, float w, float* __restrict__ field)
{
    const int i0 = max((int)floorf(x0u), 0);
    const int j0 = max((int)floorf(y0u), 0);
    const int jq0 = j0 & ~3;              // aligned quad base, <= 252: always in grid
    const int jq1 = jq0 + 4;

    float q0[4], q1[4];
    #pragma unroll
    for (int k = 0; k < 4; k++) {
        float c = (float)(jq0 + k);
        q0[k] = fmaxf(fminf(y1u, c + 1.0f) - fmaxf(y0u, c), 0.0f);
    }
    const bool use1 = (jq1 < G) && (y1u > (float)jq1);
    #pragma unroll
    for (int k = 0; k < 4; k++) {
        float c = (float)(jq1 + k);
        q1[k] = fmaxf(fminf(y1u, c + 1.0f) - fmaxf(y0u, c), 0.0f);
    }

    #pragma unroll
    for (int s = 0; s < 4; s++) {
        int i = i0 + s;
        float fi = (float)i;
        float oxu = fmaxf(fminf(x1u, fi + 1.0f) - fmaxf(x0u, fi), 0.0f);
        float sx = w * oxu;
        if (i < G && sx != 0.0f) {
            float* rowbase = field + i * G;
            red_v4(rowbase + jq0, sx * q0[0], sx * q0[1], sx * q0[2], sx * q0[3]);
            if (use1) red_v4(rowbase + jq1, sx * q1[0], sx * q1[1], sx * q1[2], sx * q1[3]);
        }
    }
}

__global__ void __launch_bounds__(256) charge_scatter_kernel(
    const float4* __restrict__ boundary,  // [xmin, ymin, xmax, ymax]
    const float4* __restrict__ xy2,       // [N/2] two rects per float4
    const float4* __restrict__ dims2,     // [N/2]
    const float2* __restrict__ cw2,       // [N/2]
    float* __restrict__ field,            // [G*G]
    int npair, int n)
{
    int t = blockIdx.x * blockDim.x + threadIdx.x;
    if (t >= npair) return;

    const float4 pq = xy2[t];     // rect A: (x,y)=(pq.x,pq.y); rect B: (pq.z,pq.w)
    const float4 dq = dims2[t];
    const float2 wq = cw2[t];

    const float4 b = *boundary;
    const float inv_lx = __frcp_rn((b.z - b.x) * (1.0f / G));  // exact: lx = 2^-8
    const float inv_ly = __frcp_rn((b.w - b.y) * (1.0f / G));

    // Rect A
    {
        float x0u = (pq.x - b.x) * inv_lx;
        float x1u = (pq.x + dq.x - b.x) * inv_lx;
        float y0u = (pq.y - b.y) * inv_ly;
        float y1u = (pq.y + dq.y - b.y) * inv_ly;
        scatter_rect(x0u, x1u, y0u, y1u, wq.x, field);
    }
    // Rect B (guard the odd-n tail)
    int rB = 2 * t + 1;
    if (rB < n) {
        float x0u = (pq.z - b.x) * inv_lx;
        float x1u = (pq.z + dq.z - b.x) * inv_lx;
        float y0u = (pq.w - b.y) * inv_ly;
        float y1u = (pq.w + dq.w - b.y) * inv_ly;
        scatter_rect(x0u, x1u, y0u, y1u, wq.y, field);
    }
}

extern "C" void kernel_launch(void* const* d_in, const int* in_sizes, int n_in,
                              void* d_out, int out_size) {
    const float4* boundary = (const float4*)d_in[0];
    const float4* xy2      = (const float4*)d_in[1];
    const float4* dims2    = (const float4*)d_in[2];
    const float2* cw2      = (const float2*)d_in[3];
    float* field = (float*)d_out;

    const int n = in_sizes[3];          // N_RECTS
    const int npair = (n + 1) / 2;

    int n4 = out_size / 4;
    zero_field_kernel4<<<(n4 + 255) / 256, 256>>>((float4*)field, n4);

    charge_scatter_kernel<<<(npair + 255) / 256, 256>>>(
        boundary, xy2, dims2, cw2, field, npair, n);
}